// round 5
// baseline (speedup 1.0000x reference)
#include <cuda_runtime.h>

#define NCL 127            // active clusters (last cluster excluded by reference)
#define NPTS 1024
#define THREADS 128        // 4 warps per CTA
#define RPT 4              // rows per thread -> 128 rows per warp, 512 per CTA
#define BIGF 3.4e38f

// Per-(cluster,half) row-term partials; per-(half,cluster) column-min partials;
// per-cluster totals.
__device__ float g_rowsum[2 * NCL];
__device__ float g_col[2 * NCL * NPTS];   // [half][c][j]
__device__ float g_cl[NCL];

// One CTA per (cluster c in [0,126], half in {0,1}); CTA covers rows
// [half*512, half*512+512) x all 1024 cols of cluster c's distance matrix
//   d(i,j) = |a_i|^2 + |b_j|^2 - 2 a_i.b_j
// Row-min (over j) and col-min (over i) extracted in ONE pass:
//   t = |b_j|^2 - 2 a.b   (3 FFMA)  -> rowmin accumulator (add |a_i|^2 at end)
//   u = t + |a_i|^2 = d   (1 FADD)  -> colmin
// Col-min across the 32 lanes uses a register "carry" passed lane-to-lane with
// __shfl_down each iteration under lane rotation jc = (j+lane) & 1023:
// column j's full min arrives at lane 0 at iteration j (mod 1024); the final
// 32 extra iterations re-complete columns 0..31 (idempotent overwrite).
__global__ void __launch_bounds__(THREADS, 2)
chamfer_main(const float* __restrict__ in_pts,
             const float* __restrict__ out_pts) {
    const int c    = blockIdx.x >> 1;
    const int half = blockIdx.x & 1;

    const float* ap = in_pts  + (size_t)c * NPTS * 3;   // rows
    const float* bp = out_pts + (size_t)c * NPTS * 3;   // cols

    __shared__ float4 sb[NPTS];        // (x,y,z,|b|^2) per column point, 16KB
    __shared__ float  wcol[4][NPTS];   // per-warp colmin partials, 16KB
    __shared__ float  rbuf[4];

    const int tid  = threadIdx.x;
    const int wid  = tid >> 5;
    const int lane = tid & 31;

    for (int j = tid; j < NPTS; j += THREADS) {
        float x = bp[3 * j + 0];
        float y = bp[3 * j + 1];
        float z = bp[3 * j + 2];
        sb[j] = make_float4(x, y, z, fmaf(x, x, fmaf(y, y, z * z)));
    }
    __syncthreads();

    // This warp's rows.
    float a2x[RPT], a2y[RPT], a2z[RPT], an[RPT], m[RPT];
#pragma unroll
    for (int r = 0; r < RPT; r++) {
        int row = half * 512 + wid * 128 + r * 32 + lane;
        float x = ap[3 * row + 0];
        float y = ap[3 * row + 1];
        float z = ap[3 * row + 2];
        a2x[r] = -2.0f * x;
        a2y[r] = -2.0f * y;
        a2z[r] = -2.0f * z;
        an[r]  = fmaf(x, x, fmaf(y, y, z * z));
        m[r]   = BIGF;
    }

    float cm = BIGF;           // traveling column-min carry
    float* mycol = wcol[wid];

#pragma unroll 4
    for (int j = 0; j < NPTS + 32; j++) {
        float4 b = sb[(j + lane) & (NPTS - 1)];
        float t0 = fmaf(a2x[0], b.x, fmaf(a2y[0], b.y, fmaf(a2z[0], b.z, b.w)));
        float t1 = fmaf(a2x[1], b.x, fmaf(a2y[1], b.y, fmaf(a2z[1], b.z, b.w)));
        float t2 = fmaf(a2x[2], b.x, fmaf(a2y[2], b.y, fmaf(a2z[2], b.z, b.w)));
        float t3 = fmaf(a2x[3], b.x, fmaf(a2y[3], b.y, fmaf(a2z[3], b.z, b.w)));
        m[0] = fminf(m[0], t0);
        m[1] = fminf(m[1], t1);
        m[2] = fminf(m[2], t2);
        m[3] = fminf(m[3], t3);
        float u0 = t0 + an[0];
        float u1 = t1 + an[1];
        float u2 = t2 + an[2];
        float u3 = t3 + an[3];
        float umin = fminf(fminf(u0, u1), fminf(u2, u3));
        cm = __shfl_down_sync(0xffffffffu, cm, 1);
        cm = (lane == 31) ? BIGF : cm;
        cm = fminf(cm, umin);
        if (lane == 0) mycol[j & (NPTS - 1)] = cm;
    }

    // Row-term partial: sum over this thread's rows of (|a|^2 + min_j t).
    float s = 0.0f;
#pragma unroll
    for (int r = 0; r < RPT; r++) s += m[r] + an[r];
#pragma unroll
    for (int off = 16; off > 0; off >>= 1)
        s += __shfl_down_sync(0xffffffffu, s, off);
    if (lane == 0) rbuf[wid] = s;
    __syncthreads();
    if (tid == 0)
        g_rowsum[blockIdx.x] = (rbuf[0] + rbuf[1]) + (rbuf[2] + rbuf[3]);

    // Column-min partial over this CTA's 512 rows: min of the 4 warp arrays.
    for (int idx = tid; idx < NPTS; idx += THREADS) {
        float v = fminf(fminf(wcol[0][idx], wcol[1][idx]),
                        fminf(wcol[2][idx], wcol[3][idx]));
        g_col[((size_t)half * NCL + c) * NPTS + idx] = v;
    }
}

// Per-cluster reduce: merge the two half colmin partials, add row partials.
__global__ void cluster_reduce_kernel() {
    const int c   = blockIdx.x;      // 0..126
    const int tid = threadIdx.x;     // 256
    const float* c0 = g_col + (size_t)c * NPTS;
    const float* c1 = g_col + (size_t)(NCL + c) * NPTS;

    float s = 0.0f;
    for (int j = tid; j < NPTS; j += 256)
        s += fminf(c0[j], c1[j]);

#pragma unroll
    for (int off = 16; off > 0; off >>= 1)
        s += __shfl_down_sync(0xffffffffu, s, off);
    __shared__ float ws[8];
    if ((tid & 31) == 0) ws[tid >> 5] = s;
    __syncthreads();
    if (tid < 8) {
        s = ws[tid];
#pragma unroll
        for (int off = 4; off > 0; off >>= 1)
            s += __shfl_down_sync(0xffu, s, off);
        if (tid == 0)
            g_cl[c] = s + g_rowsum[2 * c] + g_rowsum[2 * c + 1];
    }
}

__global__ void final_sum_kernel(float* __restrict__ out) {
    const int tid = threadIdx.x;     // 128
    float s = (tid < NCL) ? g_cl[tid] : 0.0f;
#pragma unroll
    for (int off = 16; off > 0; off >>= 1)
        s += __shfl_down_sync(0xffffffffu, s, off);
    __shared__ float ws[4];
    if ((tid & 31) == 0) ws[tid >> 5] = s;
    __syncthreads();
    if (tid == 0) out[0] = (ws[0] + ws[1]) + (ws[2] + ws[3]);
}

extern "C" void kernel_launch(void* const* d_in, const int* in_sizes, int n_in,
                              void* d_out, int out_size) {
    const float* in_pts  = (const float*)d_in[0];
    const float* out_pts = (const float*)d_in[2];
    float* out = (float*)d_out;

    chamfer_main<<<2 * NCL, THREADS>>>(in_pts, out_pts);
    cluster_reduce_kernel<<<NCL, 256>>>();
    final_sum_kernel<<<1, 128>>>(out);
}

// round 7
// speedup vs baseline: 2.4912x; 2.4912x over previous
#include <cuda_runtime.h>

#define NCL 127            // active clusters (reference excludes the last)
#define NPTS 1024
#define SLABS 16           // row slabs per cluster (64 rows each)
#define THREADS 128        // 4 warps; warp owns 16 rows
#define R 16               // rows per warp (shared across lanes)
#define BIGF 3.4e38f

// Per-(cluster,slab) colmin partials and row-term partials.
__device__ float g_col[NCL * SLABS * NPTS];   // [c][slab][j]
__device__ float g_rowsum[NCL * SLABS];
__device__ float g_cl[NCL];

// CTA = (cluster c, 64-row slab). Warp w owns rows slab*64 + w*16 .. +15,
// SHARED across its 32 lanes; lane handles columns j = 32*s + lane.
// u = d(i,j) = (|b_j|^2 + |a_i|^2) - 2 a_i.b_j, chain seeded with bw+an[r]:
//   u_r = fma(-2ax, bx, fma(-2ay, by, fma(-2az, bz, bw + an[r])))
// Row-min: lane-private partial m[r] over the lane's cols, merged once at end.
// Col-min: lane-private tree over the 16 rows, one STS per step. No per-step
// cross-lane communication at all.
__global__ void __launch_bounds__(THREADS)
chamfer_main(const float* __restrict__ in_pts,
             const float* __restrict__ out_pts) {
    const int c    = blockIdx.x >> 4;
    const int slab = blockIdx.x & (SLABS - 1);

    const float* ap = in_pts  + (size_t)c * NPTS * 3;
    const float* bp = out_pts + (size_t)c * NPTS * 3;

    __shared__ float wcol[4][NPTS];      // per-warp colmin (16 rows) per col
    __shared__ float srow[4][R][33];     // per-lane rowmin partials (padded)
    __shared__ float redbuf[4];

    const int tid  = threadIdx.x;
    const int wid  = tid >> 5;
    const int lane = tid & 31;

    // Load this warp's 16 rows (192B, 16B-aligned) via 12 uniform LDG.128.
    const float4* arow4 =
        (const float4*)(ap + ((size_t)slab * 64 + wid * R) * 3);
    float rf[48];
    {
        float4 rv[12];
#pragma unroll
        for (int k = 0; k < 12; k++) rv[k] = arow4[k];
#pragma unroll
        for (int k = 0; k < 12; k++) {
            rf[4 * k + 0] = rv[k].x;
            rf[4 * k + 1] = rv[k].y;
            rf[4 * k + 2] = rv[k].z;
            rf[4 * k + 3] = rv[k].w;
        }
    }
    float a2x[R], a2y[R], a2z[R], an[R], m[R];
#pragma unroll
    for (int r = 0; r < R; r++) {
        float x = rf[3 * r + 0];
        float y = rf[3 * r + 1];
        float z = rf[3 * r + 2];
        a2x[r] = -2.0f * x;
        a2y[r] = -2.0f * y;
        a2z[r] = -2.0f * z;
        an[r]  = fmaf(x, x, fmaf(y, y, z * z));
        m[r]   = BIGF;
    }

    // Main loop: 32 steps; lane's col j = 32*s + lane.
#pragma unroll 2
    for (int s = 0; s < NPTS / 32; s++) {
        const int j = 32 * s + lane;
        float bx = bp[3 * j + 0];
        float by = bp[3 * j + 1];
        float bz = bp[3 * j + 2];
        float bw = fmaf(bx, bx, fmaf(by, by, bz * bz));

        float u[R];
#pragma unroll
        for (int r = 0; r < R; r++) {
            u[r] = fmaf(a2x[r], bx,
                   fmaf(a2y[r], by,
                   fmaf(a2z[r], bz, bw + an[r])));
            m[r] = fminf(m[r], u[r]);
        }
        // Col-min tree over the 16 rows (lane-private).
        float c0 = fminf(fminf(u[0],  u[1]),  fminf(u[2],  u[3]));
        float c1 = fminf(fminf(u[4],  u[5]),  fminf(u[6],  u[7]));
        float c2 = fminf(fminf(u[8],  u[9]),  fminf(u[10], u[11]));
        float c3 = fminf(fminf(u[12], u[13]), fminf(u[14], u[15]));
        wcol[wid][j] = fminf(fminf(c0, c1), fminf(c2, c3));
    }

    // Dump lane-private rowmin partials.
#pragma unroll
    for (int r = 0; r < R; r++) srow[wid][r][lane] = m[r];
    __syncthreads();

    // Row phase: thread t<64 owns row t (warp t>>4, r t&15): min over 32 lanes.
    float rs = 0.0f;
    if (tid < 64) {
        const float* p = srow[tid >> 4][tid & 15];
        float v = p[0];
#pragma unroll
        for (int k = 1; k < 32; k++) v = fminf(v, p[k]);
        rs = v;
    }
    // Sum the 64 row minima (threads 64..127 contribute 0).
#pragma unroll
    for (int off = 16; off > 0; off >>= 1)
        rs += __shfl_down_sync(0xffffffffu, rs, off);
    if ((tid & 31) == 0) redbuf[wid] = rs;

    // Col phase: merge 4 warps' colmins, store slab partial to gmem.
    // (reads wcol written before the syncthreads above)
    float* gout = g_col + ((size_t)c * SLABS + slab) * NPTS;
    for (int col = tid; col < NPTS; col += THREADS) {
        float v = fminf(fminf(wcol[0][col], wcol[1][col]),
                        fminf(wcol[2][col], wcol[3][col]));
        gout[col] = v;
    }
    __syncthreads();
    if (tid == 0)
        g_rowsum[blockIdx.x] = (redbuf[0] + redbuf[1]) + redbuf[2];  // warps 0,1 hold rows; warp2/3 rs=0
}

// Per-cluster: min colmin partials over 16 slabs, sum over cols, add row terms.
__global__ void cluster_reduce_kernel() {
    const int c   = blockIdx.x;      // 0..126
    const int tid = threadIdx.x;     // 256
    const float* base = g_col + (size_t)c * SLABS * NPTS;

    float s = 0.0f;
    for (int col = tid; col < NPTS; col += 256) {
        float v = BIGF;
#pragma unroll
        for (int sl = 0; sl < SLABS; sl++)
            v = fminf(v, base[sl * NPTS + col]);
        s += v;
    }
    if (tid < SLABS) s += g_rowsum[c * SLABS + tid];

#pragma unroll
    for (int off = 16; off > 0; off >>= 1)
        s += __shfl_down_sync(0xffffffffu, s, off);
    __shared__ float ws[8];
    if ((tid & 31) == 0) ws[tid >> 5] = s;
    __syncthreads();
    if (tid < 8) {
        s = ws[tid];
#pragma unroll
        for (int off = 4; off > 0; off >>= 1)
            s += __shfl_down_sync(0xffu, s, off);
        if (tid == 0) g_cl[c] = s;
    }
}

__global__ void final_sum_kernel(float* __restrict__ out) {
    const int tid = threadIdx.x;     // 128
    float s = (tid < NCL) ? g_cl[tid] : 0.0f;
#pragma unroll
    for (int off = 16; off > 0; off >>= 1)
        s += __shfl_down_sync(0xffffffffu, s, off);
    __shared__ float ws[4];
    if ((tid & 31) == 0) ws[tid >> 5] = s;
    __syncthreads();
    if (tid == 0) out[0] = (ws[0] + ws[1]) + (ws[2] + ws[3]);
}

extern "C" void kernel_launch(void* const* d_in, const int* in_sizes, int n_in,
                              void* d_out, int out_size) {
    const float* in_pts  = (const float*)d_in[0];
    const float* out_pts = (const float*)d_in[2];
    float* out = (float*)d_out;

    chamfer_main<<<NCL * SLABS, THREADS>>>(in_pts, out_pts);
    cluster_reduce_kernel<<<NCL, 256>>>();
    final_sum_kernel<<<1, 128>>>(out);
}

// round 11
// speedup vs baseline: 2.6296x; 1.0556x over previous
#include <cuda_runtime.h>

#define NCL 127            // active clusters (reference excludes the last)
#define NPTS 1024
#define SLABS 16           // row slabs per cluster (64 rows each)
#define THREADS 128        // 4 warps; warp owns 16 rows
#define R 16               // rows per warp (shared across lanes)
#define BIGF 3.4e38f

__device__ float g_col[NCL * SLABS * NPTS];   // [c][slab][j] colmin partials
__device__ float g_rowsum[NCL * SLABS];
__device__ float g_cl[NCL];

// CTA = (cluster c, 64-row slab). Warp w owns rows slab*64 + w*16..+15 (row
// data broadcast in registers); lane owns column j = 32*s + lane at step s.
//   t_r = fma(-2ax,bx, fma(-2ay,by, fma(-2az,bz, |a|^2)))   (3 FFMA, reg seed)
//   d(r,j) = t_r + |b_j|^2
// Row-min: m[r] = fmin(m[r], t_r + bw)       (lane-private, merged via shfl at end)
// Col-min: bw + (15-FMNMX tree over t_r)     (lane-private, one STS per step)
// Columns staged in smem as float4 (x,y,z,|b|^2): inner loop has ONE LDS.128
// and zero global traffic.
__global__ void __launch_bounds__(THREADS)
chamfer_main(const float* __restrict__ in_pts,
             const float* __restrict__ out_pts) {
    const int c    = blockIdx.x >> 4;
    const int slab = blockIdx.x & (SLABS - 1);

    const float* ap = in_pts  + (size_t)c * NPTS * 3;
    const float* bp = out_pts + (size_t)c * NPTS * 3;

    __shared__ float4 sb[NPTS];     // (x,y,z,|b|^2) per column, 16KB
    __shared__ float  wcol[4][NPTS];// per-warp colmin per col, 16KB
    __shared__ float  redbuf[4];

    const int tid  = threadIdx.x;
    const int wid  = tid >> 5;
    const int lane = tid & 31;

    // Stage columns + norms.
    for (int j = tid; j < NPTS; j += THREADS) {
        float x = bp[3 * j + 0];
        float y = bp[3 * j + 1];
        float z = bp[3 * j + 2];
        sb[j] = make_float4(x, y, z, fmaf(x, x, fmaf(y, y, z * z)));
    }

    // Load this warp's 16 rows (192B, 16B-aligned) via 12 uniform LDG.128.
    const float4* arow4 =
        (const float4*)(ap + ((size_t)slab * 64 + wid * R) * 3);
    float rf[48];
    {
        float4 rv[12];
#pragma unroll
        for (int k = 0; k < 12; k++) rv[k] = arow4[k];
#pragma unroll
        for (int k = 0; k < 12; k++) {
            rf[4 * k + 0] = rv[k].x;
            rf[4 * k + 1] = rv[k].y;
            rf[4 * k + 2] = rv[k].z;
            rf[4 * k + 3] = rv[k].w;
        }
    }
    float a2x[R], a2y[R], a2z[R], an[R], m[R];
#pragma unroll
    for (int r = 0; r < R; r++) {
        float x = rf[3 * r + 0];
        float y = rf[3 * r + 1];
        float z = rf[3 * r + 2];
        a2x[r] = -2.0f * x;
        a2y[r] = -2.0f * y;
        a2z[r] = -2.0f * z;
        an[r]  = fmaf(x, x, fmaf(y, y, z * z));
        m[r]   = BIGF;
    }
    __syncthreads();

    float* mycol = wcol[wid];

    // Main loop: 32 steps; lane's col j = 32*s + lane.
#pragma unroll 2
    for (int s = 0; s < NPTS / 32; s++) {
        const int j = (s << 5) | lane;
        float4 b = sb[j];

        float t[R];
#pragma unroll
        for (int r = 0; r < R; r++) {
            t[r] = fmaf(a2x[r], b.x,
                   fmaf(a2y[r], b.y,
                   fmaf(a2z[r], b.z, an[r])));
            m[r] = fminf(m[r], t[r] + b.w);
        }
        float c0 = fminf(fminf(t[0],  t[1]),  fminf(t[2],  t[3]));
        float c1 = fminf(fminf(t[4],  t[5]),  fminf(t[6],  t[7]));
        float c2 = fminf(fminf(t[8],  t[9]),  fminf(t[10], t[11]));
        float c3 = fminf(fminf(t[12], t[13]), fminf(t[14], t[15]));
        mycol[j] = fminf(fminf(c0, c1), fminf(c2, c3)) + b.w;
    }

    // Row-min merge across lanes: butterfly per row, then sum over rows.
    float rs = 0.0f;
#pragma unroll
    for (int r = 0; r < R; r++) {
        float v = m[r];
#pragma unroll
        for (int off = 16; off > 0; off >>= 1)
            v = fminf(v, __shfl_xor_sync(0xffffffffu, v, off));
        rs += v;
    }
    if (lane == 0) redbuf[wid] = rs;
    __syncthreads();

    // Col phase: merge 4 warps' colmins, store slab partial.
    float* gout = g_col + ((size_t)c * SLABS + slab) * NPTS;
    for (int col = tid; col < NPTS; col += THREADS) {
        float v = fminf(fminf(wcol[0][col], wcol[1][col]),
                        fminf(wcol[2][col], wcol[3][col]));
        gout[col] = v;
    }
    if (tid == 0)
        g_rowsum[blockIdx.x] =
            (redbuf[0] + redbuf[1]) + (redbuf[2] + redbuf[3]);
}

// Per-cluster: min colmin partials over 16 slabs, sum over cols, add row terms.
__global__ void cluster_reduce_kernel() {
    const int c   = blockIdx.x;      // 0..126
    const int tid = threadIdx.x;     // 256
    const float* base = g_col + (size_t)c * SLABS * NPTS;

    float s = 0.0f;
    for (int col = tid; col < NPTS; col += 256) {
        float v = BIGF;
#pragma unroll
        for (int sl = 0; sl < SLABS; sl++)
            v = fminf(v, base[sl * NPTS + col]);
        s += v;
    }
    if (tid < SLABS) s += g_rowsum[c * SLABS + tid];

#pragma unroll
    for (int off = 16; off > 0; off >>= 1)
        s += __shfl_down_sync(0xffffffffu, s, off);
    __shared__ float ws[8];
    if ((tid & 31) == 0) ws[tid >> 5] = s;
    __syncthreads();
    if (tid < 8) {
        s = ws[tid];
#pragma unroll
        for (int off = 4; off > 0; off >>= 1)
            s += __shfl_down_sync(0xffu, s, off);
        if (tid == 0) g_cl[c] = s;
    }
}

__global__ void final_sum_kernel(float* __restrict__ out) {
    const int tid = threadIdx.x;     // 128
    float s = (tid < NCL) ? g_cl[tid] : 0.0f;
#pragma unroll
    for (int off = 16; off > 0; off >>= 1)
        s += __shfl_down_sync(0xffffffffu, s, off);
    __shared__ float ws[4];
    if ((tid & 31) == 0) ws[tid >> 5] = s;
    __syncthreads();
    if (tid == 0) out[0] = (ws[0] + ws[1]) + (ws[2] + ws[3]);
}

extern "C" void kernel_launch(void* const* d_in, const int* in_sizes, int n_in,
                              void* d_out, int out_size) {
    const float* in_pts  = (const float*)d_in[0];
    const float* out_pts = (const float*)d_in[2];
    float* out = (float*)d_out;

    chamfer_main<<<NCL * SLABS, THREADS>>>(in_pts, out_pts);
    cluster_reduce_kernel<<<NCL, 256>>>();
    final_sum_kernel<<<1, 128>>>(out);
}